// round 11
// baseline (speedup 1.0000x reference)
#include <cuda_runtime.h>
#include <mma.h>
#include <cstdint>
#include <math.h>

using namespace nvcuda;

// Problem constants (B=2, S=2048, H=1024, E=8, I=4096, top-2)
#define NT 4096
#define HD 1024
#define NE 8
#define ID 4096
#define NSLOT (2 * NT)

// GEMM tiling: CTA 128x128, 4 warps, warp 64x64, BK=16, 3-stage cp.async
#define TM 128
#define TN 128
#define BK 16
#define LDA 20            // As leading dim (floats); row stride 80B (16B-aligned)
#define LDB 132           // Bs leading dim (floats); row stride 528B (16B-aligned)
#define RTILES 32         // NT / TM

#define ASZ (TM * LDA)            // 2560 floats
#define BSZ (BK * LDB)            // 2112 floats
#define STAGE_F (ASZ + BSZ)       // 4672 floats
#define STAGE_B (STAGE_F * 4)     // 18688 bytes
#define ASZB (ASZ * 4)            // 10240 bytes
#define NSTAGE 3
#define SMEM_BYTES (NSTAGE * STAGE_B)   // 56064

// ---------------- static device scratch (no runtime alloc) ----------------
__device__ int   g_counts[NE];
__device__ int   g_offsets[NE + 1];
__device__ int   g_tok[NE * NT];
__device__ int   g_meta_i[NT * 4];
__device__ float g_meta_w[NT * 2];
__device__ float g_hdn[(size_t)NSLOT * ID];   // tf32-rounded silu(x@W1) rows
__device__ float g_y[(size_t)NSLOT * HD];
// tf32-pre-rounded operand copies (cp.async path needs no in-loop cvt)
__device__ float g_xr[(size_t)NT * HD];
__device__ float g_w1r[(size_t)NE * HD * ID];
__device__ float g_w2r[(size_t)NE * ID * HD];

// ---------------- helpers ----------------
__device__ __forceinline__ float rtf32(float x) {
    unsigned u;
    asm("cvt.rna.tf32.f32 %0, %1;" : "=r"(u) : "f"(x));
    return __uint_as_float(u);
}
__device__ __forceinline__ float4 rtf32_4(float4 v) {
    return make_float4(rtf32(v.x), rtf32(v.y), rtf32(v.z), rtf32(v.w));
}
__device__ __forceinline__ uint32_t smem_u32(const void* p) {
    uint32_t a;
    asm("{ .reg .u64 t; cvta.to.shared.u64 t, %1; cvt.u32.u64 %0, t; }" : "=r"(a) : "l"(p));
    return a;
}
// 16B async copy; bytes==0 -> zero-fill destination
__device__ __forceinline__ void cp16(uint32_t dst, const float* src, uint32_t bytes) {
    asm volatile("cp.async.cg.shared.global [%0], [%1], 16, %2;"
                 :: "r"(dst), "l"(src), "r"(bytes) : "memory");
}
#define CP_COMMIT() asm volatile("cp.async.commit_group;" ::: "memory")

// ---------------- reset / gate / prefix ----------------
__global__ void reset_kernel() {
    if (threadIdx.x < NE) g_counts[threadIdx.x] = 0;
}

__global__ void gate_kernel(const float* __restrict__ x, const float* __restrict__ Wg) {
    int warp = (blockIdx.x * blockDim.x + threadIdx.x) >> 5;
    int lane = threadIdx.x & 31;
    if (warp >= NT) return;
    const float* xr = x + (size_t)warp * HD;

    float acc[NE];
#pragma unroll
    for (int i = 0; i < NE; i++) acc[i] = 0.f;
    for (int j = lane; j < HD; j += 32) {
        float xv = xr[j];
        const float4* w4 = reinterpret_cast<const float4*>(Wg + j * NE);
        float4 wa = w4[0], wb = w4[1];
        acc[0] += xv * wa.x; acc[1] += xv * wa.y;
        acc[2] += xv * wa.z; acc[3] += xv * wa.w;
        acc[4] += xv * wb.x; acc[5] += xv * wb.y;
        acc[6] += xv * wb.z; acc[7] += xv * wb.w;
    }
#pragma unroll
    for (int i = 0; i < NE; i++) {
#pragma unroll
        for (int o = 16; o > 0; o >>= 1)
            acc[i] += __shfl_xor_sync(0xffffffffu, acc[i], o);
    }
    if (lane == 0) {
        int i0 = 0; float m0 = acc[0];
#pragma unroll
        for (int i = 1; i < NE; i++) if (acc[i] > m0) { m0 = acc[i]; i0 = i; }
        int i1 = -1; float m1 = -1e30f;
#pragma unroll
        for (int i = 0; i < NE; i++)
            if (i != i0 && acc[i] > m1) { m1 = acc[i]; i1 = i; }
        float w0 = 1.f / (1.f + expf(m1 - m0));
        float w1 = 1.f - w0;
        int s0 = atomicAdd(&g_counts[i0], 1);
        int s1 = atomicAdd(&g_counts[i1], 1);
        g_tok[i0 * NT + s0] = warp;
        g_tok[i1 * NT + s1] = warp;
        g_meta_i[warp * 4 + 0] = i0;
        g_meta_i[warp * 4 + 1] = s0;
        g_meta_i[warp * 4 + 2] = i1;
        g_meta_i[warp * 4 + 3] = s1;
        g_meta_w[warp * 2 + 0] = w0;
        g_meta_w[warp * 2 + 1] = w1;
    }
}

__global__ void prefix_kernel() {
    if (threadIdx.x == 0) {
        int s = 0;
        g_offsets[0] = 0;
        for (int e = 0; e < NE; e++) { s += g_counts[e]; g_offsets[e + 1] = s; }
    }
}

// ---------------- tf32 pre-round pass (grid-stride, float4) ----------------
__global__ void round_kernel(const float4* __restrict__ src, float4* __restrict__ dst, int n4) {
    int i = blockIdx.x * blockDim.x + threadIdx.x;
    int stride = gridDim.x * blockDim.x;
    for (; i < n4; i += stride) dst[i] = rtf32_4(src[i]);
}

// ---------------- grouped GEMM (MODE 0 = up+SiLU, 1 = down) ----------------
// A,W pre-rounded to tf32. cp.async staging, 3-stage, 64x64 warp tiles.
template <int MODE>
__global__ __launch_bounds__(128, 2) void gemm_tc(
    const float* __restrict__ A, const float* __restrict__ W,
    const float* __restrict__ bias)
{
    extern __shared__ float sh[];
    const int KS  = (MODE == 0) ? HD : ID;   // K extent (A row length)
    const int NSW = (MODE == 0) ? ID : HD;   // W row length (N extent)
    const int KT  = KS / BK;

    int e  = blockIdx.x / RTILES;
    int rt = blockIdx.x % RTILES;
    int n_e = g_counts[e];
    int row0 = rt * TM;
    if (row0 >= n_e) return;
    int n0 = blockIdx.y * TN;
    int tid = threadIdx.x;
    uint32_t sb = smem_u32(sh);

    // this thread stages A row `tid` and B row (tid>>3), cols (tid&7)*16..+15
    const float* aptr = nullptr;
    {
        int gs = row0 + tid;
        if (gs < n_e) {
            if (MODE == 0) aptr = A + (size_t)g_tok[e * NT + gs] * HD;
            else           aptr = A + (size_t)(g_offsets[e] + gs) * ID;
        }
    }
    const float* wbase = W + (size_t)e * HD * ID
                           + (size_t)(tid >> 3) * NSW + n0 + (tid & 7) * 16;
    uint32_t a_dst = sb + tid * 80;                               // row stride 80B
    uint32_t b_dst = sb + ASZB + (tid >> 3) * 528 + (tid & 7) * 64;
    uint32_t avalid = aptr ? 16u : 0u;
    const float* adummy = W;   // safe address when row invalid (bytes=0 -> zero-fill)

    auto issue = [&](int kt) {
        uint32_t so = (uint32_t)((kt % NSTAGE) * STAGE_B);
        int k0 = kt * BK;
        const float* as = aptr ? (aptr + k0) : adummy;
#pragma unroll
        for (int g = 0; g < 4; ++g)
            cp16(a_dst + so + g * 16, as + g * 4, avalid);
        const float* bs = wbase + (size_t)k0 * NSW;
#pragma unroll
        for (int g = 0; g < 4; ++g)
            cp16(b_dst + so + g * 16, bs + g * 4, 16u);
        CP_COMMIT();
    };

    int wrp = tid >> 5, wm = wrp >> 1, wn = wrp & 1, lane = tid & 31;

    wmma::fragment<wmma::accumulator, 16, 16, 8, float> c[4][4];
#pragma unroll
    for (int i = 0; i < 4; i++)
#pragma unroll
        for (int j = 0; j < 4; j++) wmma::fill_fragment(c[i][j], 0.f);

    issue(0);
    issue(1);

    for (int kt = 0; kt < KT; ++kt) {
        if (kt + 1 < KT) asm volatile("cp.async.wait_group 1;" ::: "memory");
        else             asm volatile("cp.async.wait_group 0;" ::: "memory");
        __syncthreads();                 // stage kt visible to all; prior reads retired
        if (kt + 2 < KT) issue(kt + 2);  // overwrites slot last read at kt-1 (safe)

        const float* As = sh + (kt % NSTAGE) * STAGE_F;
        const float* Bs = As + ASZ;
#pragma unroll
        for (int kk = 0; kk < 2; ++kk) {
            wmma::fragment<wmma::matrix_a, 16, 16, 8, wmma::precision::tf32, wmma::row_major> af[4];
            wmma::fragment<wmma::matrix_b, 16, 16, 8, wmma::precision::tf32, wmma::row_major> bf[4];
#pragma unroll
            for (int i = 0; i < 4; i++)
                wmma::load_matrix_sync(af[i], &As[(wm * 64 + i * 16) * LDA + kk * 8], LDA);
#pragma unroll
            for (int j = 0; j < 4; j++)
                wmma::load_matrix_sync(bf[j], &Bs[(kk * 8) * LDB + wn * 64 + j * 16], LDB);
#pragma unroll
            for (int i = 0; i < 4; i++)
#pragma unroll
                for (int j = 0; j < 4; j++)
                    wmma::mma_sync(c[i][j], af[i], bf[j], c[i][j]);
        }
    }
    __syncthreads();   // all MMAs done; stage smem reusable as epilogue patch

    int base_row = g_offsets[e] + row0;
    float* patch = sh + wrp * 320;       // 16x20 per warp
#pragma unroll
    for (int i = 0; i < 4; i++) {
#pragma unroll
        for (int j = 0; j < 4; j++) {
            wmma::store_matrix_sync(patch, c[i][j], 20, wmma::mem_row_major);
            __syncwarp();
            int lrb = wm * 64 + i * 16;
            int lcb = wn * 64 + j * 16;
#pragma unroll
            for (int q = 0; q < 8; q++) {
                int el = lane + q * 32;
                int r = el >> 4, cc = el & 15;
                int lr = lrb + r;
                if (row0 + lr < n_e) {
                    int gc = n0 + lcb + cc;
                    if (MODE == 0) {
                        float v = patch[r * 20 + cc] + bias[(size_t)e * ID + gc];
                        float sv = v / (1.f + expf(-v));
                        g_hdn[(size_t)(base_row + lr) * ID + gc] = rtf32(sv);
                    } else {
                        g_y[(size_t)(base_row + lr) * HD + gc] = patch[r * 20 + cc];
                    }
                }
            }
            __syncwarp();
        }
    }
}

// ---------------- deterministic per-token combine ----------------
__global__ void combine_kernel(const float* __restrict__ b2, float* __restrict__ out) {
    int t = blockIdx.x;
    int e0 = g_meta_i[t * 4 + 0], s0 = g_meta_i[t * 4 + 1];
    int e1 = g_meta_i[t * 4 + 2], s1 = g_meta_i[t * 4 + 3];
    float w0 = g_meta_w[t * 2 + 0];
    float w1 = g_meta_w[t * 2 + 1];
    int r0 = g_offsets[e0] + s0;
    int r1 = g_offsets[e1] + s1;

    const float4* y0 = reinterpret_cast<const float4*>(g_y + (size_t)r0 * HD);
    const float4* y1 = reinterpret_cast<const float4*>(g_y + (size_t)r1 * HD);
    const float4* c0 = reinterpret_cast<const float4*>(b2 + (size_t)e0 * HD);
    const float4* c1 = reinterpret_cast<const float4*>(b2 + (size_t)e1 * HD);
    float4* o = reinterpret_cast<float4*>(out + (size_t)t * HD);

    int h = threadIdx.x;  // blockDim = 256 == HD/4
    float4 a = y0[h], b = y1[h], p = c0[h], q = c1[h];
    float4 rr;
    rr.x = w0 * (a.x + p.x) + w1 * (b.x + q.x);
    rr.y = w0 * (a.y + p.y) + w1 * (b.y + q.y);
    rr.z = w0 * (a.z + p.z) + w1 * (b.z + q.z);
    rr.w = w0 * (a.w + p.w) + w1 * (b.w + q.w);
    o[h] = rr;
}

// ---------------- launch ----------------
extern "C" void kernel_launch(void* const* d_in, const int* in_sizes, int n_in,
                              void* d_out, int out_size) {
    const float* x  = (const float*)d_in[0];
    const float* Wg = (const float*)d_in[1];
    const float* W1 = (const float*)d_in[2];
    const float* b1 = (const float*)d_in[3];
    const float* W2 = (const float*)d_in[4];
    const float* b2 = (const float*)d_in[5];
    float* out = (float*)d_out;

    cudaFuncSetAttribute(gemm_tc<0>, cudaFuncAttributeMaxDynamicSharedMemorySize, SMEM_BYTES);
    cudaFuncSetAttribute(gemm_tc<1>, cudaFuncAttributeMaxDynamicSharedMemorySize, SMEM_BYTES);

    // Device addresses of __device__ symbols (host-side symbol names are NOT
    // device pointers — R10's bug was passing g_hdn directly).
    float* xr  = nullptr; cudaGetSymbolAddress((void**)&xr,  g_xr);
    float* w1r = nullptr; cudaGetSymbolAddress((void**)&w1r, g_w1r);
    float* w2r = nullptr; cudaGetSymbolAddress((void**)&w2r, g_w2r);
    float* hdn = nullptr; cudaGetSymbolAddress((void**)&hdn, g_hdn);

    reset_kernel<<<1, 32>>>();
    gate_kernel<<<NT / 8, 256>>>(x, Wg);
    prefix_kernel<<<1, 32>>>();

    round_kernel<<<2048, 256>>>((const float4*)x,  (float4*)xr,  NT * HD / 4);
    round_kernel<<<4096, 256>>>((const float4*)W1, (float4*)w1r, NE * HD * ID / 4);
    round_kernel<<<4096, 256>>>((const float4*)W2, (float4*)w2r, NE * ID * HD / 4);

    gemm_tc<0><<<dim3(NE * RTILES, ID / TN), 128, SMEM_BYTES>>>(xr,  w1r, b1);
    gemm_tc<1><<<dim3(NE * RTILES, HD / TN), 128, SMEM_BYTES>>>(hdn, w2r, b1);
    combine_kernel<<<NT, 256>>>(b2, out);
}

// round 12
// speedup vs baseline: 1.5520x; 1.5520x over previous
#include <cuda_runtime.h>
#include <mma.h>
#include <cstdint>
#include <math.h>

using namespace nvcuda;

// Problem constants (B=2, S=2048, H=1024, E=8, I=4096, top-2)
#define NT 4096
#define HD 1024
#define NE 8
#define ID 4096
#define NSLOT (2 * NT)

// GEMM tiling: CTA 128x128, 8 warps, warp 32x64, BK=16, 4-stage cp.async
#define TM 128
#define TN 128
#define BK 16
#define LDA 20            // As leading dim (floats); row stride 80B
#define LDB 132           // Bs leading dim (floats); row stride 528B
#define RTILES 32         // NT / TM

#define ASZ (TM * LDA)            // 2560 floats
#define BSZ (BK * LDB)            // 2112 floats
#define STAGE_F (ASZ + BSZ)       // 4672 floats
#define STAGE_B (STAGE_F * 4)     // 18688 bytes
#define ASZB (ASZ * 4)            // 10240 bytes
#define NSTAGE 4
#define SMEM_BYTES (NSTAGE * STAGE_B)   // 74752

// ---------------- static device scratch (no runtime alloc) ----------------
__device__ int   g_counts[NE];
__device__ int   g_offsets[NE + 1];
__device__ int   g_tok[NE * NT];
__device__ int   g_meta_i[NT * 4];
__device__ float g_meta_w[NT * 2];
__device__ float g_hdn[(size_t)NSLOT * ID];   // tf32-rounded silu(x@W1) rows
__device__ float g_y[(size_t)NSLOT * HD];
// tf32-pre-rounded operand copies
__device__ float g_xr[(size_t)NT * HD];
__device__ float g_w1r[(size_t)NE * HD * ID];
__device__ float g_w2r[(size_t)NE * ID * HD];

// ---------------- helpers ----------------
__device__ __forceinline__ float rtf32(float x) {
    unsigned u;
    asm("cvt.rna.tf32.f32 %0, %1;" : "=r"(u) : "f"(x));
    return __uint_as_float(u);
}
__device__ __forceinline__ float4 rtf32_4(float4 v) {
    return make_float4(rtf32(v.x), rtf32(v.y), rtf32(v.z), rtf32(v.w));
}
__device__ __forceinline__ uint32_t smem_u32(const void* p) {
    uint32_t a;
    asm("{ .reg .u64 t; cvta.to.shared.u64 t, %1; cvt.u32.u64 %0, t; }" : "=r"(a) : "l"(p));
    return a;
}
// 16B async copy; bytes==0 -> zero-fill destination
__device__ __forceinline__ void cp16(uint32_t dst, const float* src, uint32_t bytes) {
    asm volatile("cp.async.cg.shared.global [%0], [%1], 16, %2;"
                 :: "r"(dst), "l"(src), "r"(bytes) : "memory");
}
#define CP_COMMIT() asm volatile("cp.async.commit_group;" ::: "memory")

// ---------------- reset / gate / prefix ----------------
__global__ void reset_kernel() {
    if (threadIdx.x < NE) g_counts[threadIdx.x] = 0;
}

__global__ void gate_kernel(const float* __restrict__ x, const float* __restrict__ Wg) {
    int warp = (blockIdx.x * blockDim.x + threadIdx.x) >> 5;
    int lane = threadIdx.x & 31;
    if (warp >= NT) return;
    const float* xr = x + (size_t)warp * HD;

    float acc[NE];
#pragma unroll
    for (int i = 0; i < NE; i++) acc[i] = 0.f;
    for (int j = lane; j < HD; j += 32) {
        float xv = xr[j];
        const float4* w4 = reinterpret_cast<const float4*>(Wg + j * NE);
        float4 wa = w4[0], wb = w4[1];
        acc[0] += xv * wa.x; acc[1] += xv * wa.y;
        acc[2] += xv * wa.z; acc[3] += xv * wa.w;
        acc[4] += xv * wb.x; acc[5] += xv * wb.y;
        acc[6] += xv * wb.z; acc[7] += xv * wb.w;
    }
#pragma unroll
    for (int i = 0; i < NE; i++) {
#pragma unroll
        for (int o = 16; o > 0; o >>= 1)
            acc[i] += __shfl_xor_sync(0xffffffffu, acc[i], o);
    }
    if (lane == 0) {
        int i0 = 0; float m0 = acc[0];
#pragma unroll
        for (int i = 1; i < NE; i++) if (acc[i] > m0) { m0 = acc[i]; i0 = i; }
        int i1 = -1; float m1 = -1e30f;
#pragma unroll
        for (int i = 0; i < NE; i++)
            if (i != i0 && acc[i] > m1) { m1 = acc[i]; i1 = i; }
        float w0 = 1.f / (1.f + expf(m1 - m0));
        float w1 = 1.f - w0;
        int s0 = atomicAdd(&g_counts[i0], 1);
        int s1 = atomicAdd(&g_counts[i1], 1);
        g_tok[i0 * NT + s0] = warp;
        g_tok[i1 * NT + s1] = warp;
        g_meta_i[warp * 4 + 0] = i0;
        g_meta_i[warp * 4 + 1] = s0;
        g_meta_i[warp * 4 + 2] = i1;
        g_meta_i[warp * 4 + 3] = s1;
        g_meta_w[warp * 2 + 0] = w0;
        g_meta_w[warp * 2 + 1] = w1;
    }
}

__global__ void prefix_kernel() {
    if (threadIdx.x == 0) {
        int s = 0;
        g_offsets[0] = 0;
        for (int e = 0; e < NE; e++) { s += g_counts[e]; g_offsets[e + 1] = s; }
    }
}

// ---------------- fused tf32 pre-round (x, W1, W2 in one launch) ----------------
__global__ void round3_kernel(const float4* __restrict__ s0, float4* __restrict__ d0, int n0,
                              const float4* __restrict__ s1, float4* __restrict__ d1, int n1,
                              const float4* __restrict__ s2, float4* __restrict__ d2, int n2)
{
    int total = n0 + n1 + n2;
    int stride = gridDim.x * blockDim.x;
    for (int i = blockIdx.x * blockDim.x + threadIdx.x; i < total; i += stride) {
        if (i < n0)           d0[i] = rtf32_4(s0[i]);
        else if (i < n0 + n1) d1[i - n0] = rtf32_4(s1[i - n0]);
        else                  d2[i - n0 - n1] = rtf32_4(s2[i - n0 - n1]);
    }
}

// ---------------- grouped GEMM (MODE 0 = up+SiLU, 1 = down) ----------------
// A,W pre-rounded tf32. cp.async staging, 4-stage, 256 threads, 32x64 warp tiles.
template <int MODE>
__global__ __launch_bounds__(256, 2) void gemm_tc(
    const float* __restrict__ A, const float* __restrict__ W,
    const float* __restrict__ bias)
{
    extern __shared__ float sh[];
    const int KS  = (MODE == 0) ? HD : ID;   // K extent (A row length)
    const int NSW = (MODE == 0) ? ID : HD;   // W row length (N extent)
    const int KT  = KS / BK;

    int e  = blockIdx.x / RTILES;
    int rt = blockIdx.x % RTILES;
    int n_e = g_counts[e];
    int row0 = rt * TM;
    if (row0 >= n_e) return;
    int n0 = blockIdx.y * TN;
    int tid = threadIdx.x;
    uint32_t sb = smem_u32(sh);

    // A staging: 2 threads per row (tid>>1 = row, tid&1 = 32B half)
    const float* aptr = nullptr;
    {
        int gs = row0 + (tid >> 1);
        if (gs < n_e) {
            if (MODE == 0) aptr = A + (size_t)g_tok[e * NT + gs] * HD;
            else           aptr = A + (size_t)(g_offsets[e] + gs) * ID;
        }
    }
    int ahalf = tid & 1;
    uint32_t a_dst = sb + (tid >> 1) * 80 + ahalf * 32;
    uint32_t avalid = aptr ? 16u : 0u;
    const float* adummy = W;

    // B staging: 16 threads per row (tid>>4 = row 0..15, tid&15 = 32B seg)
    int brow = tid >> 4, bseg = tid & 15;
    const float* wbase = W + (size_t)e * HD * ID
                           + (size_t)brow * NSW + n0 + bseg * 8;
    uint32_t b_dst = sb + ASZB + brow * 528 + bseg * 32;

    auto issue = [&](int kt) {
        uint32_t so = (uint32_t)((kt & (NSTAGE - 1)) * STAGE_B);
        int k0 = kt * BK;
        const float* as = aptr ? (aptr + k0 + ahalf * 8) : adummy;
        cp16(a_dst + so,      as,     avalid);
        cp16(a_dst + so + 16, as + 4, avalid);
        const float* bs = wbase + (size_t)k0 * NSW;
        cp16(b_dst + so,      bs,     16u);
        cp16(b_dst + so + 16, bs + 4, 16u);
        CP_COMMIT();
    };

    int wrp = tid >> 5, wm = wrp >> 1, wn = wrp & 1, lane = tid & 31;

    wmma::fragment<wmma::accumulator, 16, 16, 8, float> c[2][4];
#pragma unroll
    for (int i = 0; i < 2; i++)
#pragma unroll
        for (int j = 0; j < 4; j++) wmma::fill_fragment(c[i][j], 0.f);

    issue(0);
    if (KT > 1) issue(1);
    if (KT > 2) issue(2);

    for (int kt = 0; kt < KT; ++kt) {
        // groups newer than kt already issued: min(kt+2, KT-1) - kt
        if (kt + 2 < KT)      asm volatile("cp.async.wait_group 2;" ::: "memory");
        else if (kt + 1 < KT) asm volatile("cp.async.wait_group 1;" ::: "memory");
        else                  asm volatile("cp.async.wait_group 0;" ::: "memory");
        __syncthreads();                 // stage kt visible; stage (kt+3)%4 readers retired
        if (kt + 3 < KT) issue(kt + 3);

        const float* As = sh + (kt & (NSTAGE - 1)) * STAGE_F;
        const float* Bs = As + ASZ;
#pragma unroll
        for (int kk = 0; kk < 2; ++kk) {
            wmma::fragment<wmma::matrix_a, 16, 16, 8, wmma::precision::tf32, wmma::row_major> af[2];
            wmma::fragment<wmma::matrix_b, 16, 16, 8, wmma::precision::tf32, wmma::row_major> bf[4];
#pragma unroll
            for (int i = 0; i < 2; i++)
                wmma::load_matrix_sync(af[i], &As[(wm * 32 + i * 16) * LDA + kk * 8], LDA);
#pragma unroll
            for (int j = 0; j < 4; j++)
                wmma::load_matrix_sync(bf[j], &Bs[(kk * 8) * LDB + wn * 64 + j * 16], LDB);
#pragma unroll
            for (int i = 0; i < 2; i++)
#pragma unroll
                for (int j = 0; j < 4; j++)
                    wmma::mma_sync(c[i][j], af[i], bf[j], c[i][j]);
        }
    }
    __syncthreads();   // all MMAs done; stage smem reusable as epilogue patch

    int base_row = g_offsets[e] + row0;
    float* patch = sh + wrp * 320;       // 16x20 per warp
#pragma unroll
    for (int i = 0; i < 2; i++) {
#pragma unroll
        for (int j = 0; j < 4; j++) {
            wmma::store_matrix_sync(patch, c[i][j], 20, wmma::mem_row_major);
            __syncwarp();
            int lrb = wm * 32 + i * 16;
            int lcb = wn * 64 + j * 16;
#pragma unroll
            for (int q = 0; q < 8; q++) {
                int el = lane + q * 32;
                int r = el >> 4, cc = el & 15;
                int lr = lrb + r;
                if (row0 + lr < n_e) {
                    int gc = n0 + lcb + cc;
                    if (MODE == 0) {
                        float v = patch[r * 20 + cc] + bias[(size_t)e * ID + gc];
                        float sv = v / (1.f + expf(-v));
                        g_hdn[(size_t)(base_row + lr) * ID + gc] = rtf32(sv);
                    } else {
                        g_y[(size_t)(base_row + lr) * HD + gc] = patch[r * 20 + cc];
                    }
                }
            }
            __syncwarp();
        }
    }
}

// ---------------- deterministic per-token combine ----------------
__global__ void combine_kernel(const float* __restrict__ b2, float* __restrict__ out) {
    int t = blockIdx.x;
    int e0 = g_meta_i[t * 4 + 0], s0 = g_meta_i[t * 4 + 1];
    int e1 = g_meta_i[t * 4 + 2], s1 = g_meta_i[t * 4 + 3];
    float w0 = g_meta_w[t * 2 + 0];
    float w1 = g_meta_w[t * 2 + 1];
    int r0 = g_offsets[e0] + s0;
    int r1 = g_offsets[e1] + s1;

    const float4* y0 = reinterpret_cast<const float4*>(g_y + (size_t)r0 * HD);
    const float4* y1 = reinterpret_cast<const float4*>(g_y + (size_t)r1 * HD);
    const float4* c0 = reinterpret_cast<const float4*>(b2 + (size_t)e0 * HD);
    const float4* c1 = reinterpret_cast<const float4*>(b2 + (size_t)e1 * HD);
    float4* o = reinterpret_cast<float4*>(out + (size_t)t * HD);

    int h = threadIdx.x;  // blockDim = 256 == HD/4
    float4 a = y0[h], b = y1[h], p = c0[h], q = c1[h];
    float4 rr;
    rr.x = w0 * (a.x + p.x) + w1 * (b.x + q.x);
    rr.y = w0 * (a.y + p.y) + w1 * (b.y + q.y);
    rr.z = w0 * (a.z + p.z) + w1 * (b.z + q.z);
    rr.w = w0 * (a.w + p.w) + w1 * (b.w + q.w);
    o[h] = rr;
}

// ---------------- launch ----------------
extern "C" void kernel_launch(void* const* d_in, const int* in_sizes, int n_in,
                              void* d_out, int out_size) {
    const float* x  = (const float*)d_in[0];
    const float* Wg = (const float*)d_in[1];
    const float* W1 = (const float*)d_in[2];
    const float* b1 = (const float*)d_in[3];
    const float* W2 = (const float*)d_in[4];
    const float* b2 = (const float*)d_in[5];
    float* out = (float*)d_out;

    cudaFuncSetAttribute(gemm_tc<0>, cudaFuncAttributeMaxDynamicSharedMemorySize, SMEM_BYTES);
    cudaFuncSetAttribute(gemm_tc<1>, cudaFuncAttributeMaxDynamicSharedMemorySize, SMEM_BYTES);

    // Device addresses of __device__ symbols (host symbol names are not device ptrs)
    float* xr  = nullptr; cudaGetSymbolAddress((void**)&xr,  g_xr);
    float* w1r = nullptr; cudaGetSymbolAddress((void**)&w1r, g_w1r);
    float* w2r = nullptr; cudaGetSymbolAddress((void**)&w2r, g_w2r);
    float* hdn = nullptr; cudaGetSymbolAddress((void**)&hdn, g_hdn);

    // 7 launches total; ncu -s 5 -c 1 captures launch #6 = gemm_tc<1> (down GEMM)
    reset_kernel<<<1, 32>>>();
    gate_kernel<<<NT / 8, 256>>>(x, Wg);
    prefix_kernel<<<1, 32>>>();
    round3_kernel<<<8192, 256>>>(
        (const float4*)x,  (float4*)xr,  NT * HD / 4,
        (const float4*)W1, (float4*)w1r, NE * HD * ID / 4,
        (const float4*)W2, (float4*)w2r, NE * ID * HD / 4);
    gemm_tc<0><<<dim3(NE * RTILES, ID / TN), 256, SMEM_BYTES>>>(xr,  w1r, b1);
    gemm_tc<1><<<dim3(NE * RTILES, HD / TN), 256, SMEM_BYTES>>>(hdn, w2r, b1);
    combine_kernel<<<NT, 256>>>(b2, out);
}

// round 14
// speedup vs baseline: 5.1234x; 3.3012x over previous
#include <cuda_runtime.h>
#include <cuda_fp16.h>
#include <mma.h>
#include <cstdint>
#include <math.h>

using namespace nvcuda;

// Problem constants (B=2, S=2048, H=1024, E=8, I=4096, top-2)
#define NT 4096
#define HD 1024
#define NE 8
#define ID 4096
#define NSLOT (2 * NT)

// GEMM tiling: CTA 128x128, 8 warps, warp 32x64, BK=32 (fp16), 4-stage cp.async
#define TM 128
#define TN 128
#define BK 32
#define LDA 40            // As leading dim (halfs); row stride 80B
#define LDB 136           // Bs leading dim (halfs); row stride 272B
#define RTILES 32         // NT / TM

#define ASZ (TM * LDA)            // 5120 halfs
#define BSZ (BK * LDB)            // 4352 halfs
#define STAGE_H (ASZ + BSZ)       // 9472 halfs
#define STAGE_B (STAGE_H * 2)     // 18944 bytes
#define ASZB (ASZ * 2)            // 10240 bytes
#define NSTAGE 4
#define SMEM_BYTES (NSTAGE * STAGE_B)   // 75776

// ---------------- static device scratch (no runtime alloc) ----------------
__device__ int    g_counts[NE];
__device__ int    g_offsets[NE + 1];
__device__ int    g_tok[NE * NT];
__device__ int    g_meta_i[NT * 4];
__device__ float  g_meta_w[NT * 2];
__device__ __half g_hdn[(size_t)NSLOT * ID];   // fp16 silu(x@W1) rows (compacted)
__device__ float  g_y[(size_t)NSLOT * HD];
// fp16 operand copies
__device__ __half g_xh[(size_t)NT * HD];
__device__ __half g_w1h[(size_t)NE * HD * ID];
__device__ __half g_w2h[(size_t)NE * ID * HD];

// ---------------- helpers ----------------
__device__ __forceinline__ uint32_t smem_u32(const void* p) {
    uint32_t a;
    asm("{ .reg .u64 t; cvta.to.shared.u64 t, %1; cvt.u32.u64 %0, t; }" : "=r"(a) : "l"(p));
    return a;
}
// 16B async copy; bytes==0 -> zero-fill destination
__device__ __forceinline__ void cp16(uint32_t dst, const void* src, uint32_t bytes) {
    asm volatile("cp.async.cg.shared.global [%0], [%1], 16, %2;"
                 :: "r"(dst), "l"(src), "r"(bytes) : "memory");
}
#define CP_COMMIT() asm volatile("cp.async.commit_group;" ::: "memory")

struct __align__(8) h4 { __half2 a, b; };

// ---------------- reset / gate / prefix ----------------
__global__ void reset_kernel() {
    if (threadIdx.x < NE) g_counts[threadIdx.x] = 0;
}

__global__ void gate_kernel(const float* __restrict__ x, const float* __restrict__ Wg) {
    int warp = (blockIdx.x * blockDim.x + threadIdx.x) >> 5;
    int lane = threadIdx.x & 31;
    if (warp >= NT) return;
    const float* xr = x + (size_t)warp * HD;

    float acc[NE];
#pragma unroll
    for (int i = 0; i < NE; i++) acc[i] = 0.f;
    for (int j = lane; j < HD; j += 32) {
        float xv = xr[j];
        const float4* w4 = reinterpret_cast<const float4*>(Wg + j * NE);
        float4 wa = w4[0], wb = w4[1];
        acc[0] += xv * wa.x; acc[1] += xv * wa.y;
        acc[2] += xv * wa.z; acc[3] += xv * wa.w;
        acc[4] += xv * wb.x; acc[5] += xv * wb.y;
        acc[6] += xv * wb.z; acc[7] += xv * wb.w;
    }
#pragma unroll
    for (int i = 0; i < NE; i++) {
#pragma unroll
        for (int o = 16; o > 0; o >>= 1)
            acc[i] += __shfl_xor_sync(0xffffffffu, acc[i], o);
    }
    if (lane == 0) {
        int i0 = 0; float m0 = acc[0];
#pragma unroll
        for (int i = 1; i < NE; i++) if (acc[i] > m0) { m0 = acc[i]; i0 = i; }
        int i1 = -1; float m1 = -1e30f;
#pragma unroll
        for (int i = 0; i < NE; i++)
            if (i != i0 && acc[i] > m1) { m1 = acc[i]; i1 = i; }
        float w0 = 1.f / (1.f + expf(m1 - m0));
        float w1 = 1.f - w0;
        int s0 = atomicAdd(&g_counts[i0], 1);
        int s1 = atomicAdd(&g_counts[i1], 1);
        g_tok[i0 * NT + s0] = warp;
        g_tok[i1 * NT + s1] = warp;
        g_meta_i[warp * 4 + 0] = i0;
        g_meta_i[warp * 4 + 1] = s0;
        g_meta_i[warp * 4 + 2] = i1;
        g_meta_i[warp * 4 + 3] = s1;
        g_meta_w[warp * 2 + 0] = w0;
        g_meta_w[warp * 2 + 1] = w1;
    }
}

__global__ void prefix_kernel() {
    if (threadIdx.x == 0) {
        int s = 0;
        g_offsets[0] = 0;
        for (int e = 0; e < NE; e++) { s += g_counts[e]; g_offsets[e + 1] = s; }
    }
}

// ---------------- fused fp32 -> fp16 convert (x, W1, W2 in one launch) ----------------
__global__ void conv3_kernel(const float4* __restrict__ s0, h4* __restrict__ d0, int n0,
                             const float4* __restrict__ s1, h4* __restrict__ d1, int n1,
                             const float4* __restrict__ s2, h4* __restrict__ d2, int n2)
{
    int total = n0 + n1 + n2;
    int stride = gridDim.x * blockDim.x;
    for (int i = blockIdx.x * blockDim.x + threadIdx.x; i < total; i += stride) {
        if (i < n0) {
            float4 v = s0[i];
            h4 o; o.a = __floats2half2_rn(v.x, v.y); o.b = __floats2half2_rn(v.z, v.w);
            d0[i] = o;
        } else if (i < n0 + n1) {
            int k = i - n0;
            float4 v = s1[k];
            h4 o; o.a = __floats2half2_rn(v.x, v.y); o.b = __floats2half2_rn(v.z, v.w);
            d1[k] = o;
        } else {
            int k = i - n0 - n1;
            float4 v = s2[k];
            h4 o; o.a = __floats2half2_rn(v.x, v.y); o.b = __floats2half2_rn(v.z, v.w);
            d2[k] = o;
        }
    }
}

// ---------------- grouped GEMM (MODE 0 = up+SiLU, 1 = down), fp16 MMA ----------------
template <int MODE>
__global__ __launch_bounds__(256, 2) void gemm_tc(
    const __half* __restrict__ A, const __half* __restrict__ W,
    const float* __restrict__ bias)
{
    extern __shared__ __align__(16) char smem[];
    __half* sh = reinterpret_cast<__half*>(smem);
    const int KS  = (MODE == 0) ? HD : ID;   // K extent (A row length)
    const int NSW = (MODE == 0) ? ID : HD;   // W row length (N extent)
    const int KT  = KS / BK;

    int e  = blockIdx.x / RTILES;
    int rt = blockIdx.x % RTILES;
    int n_e = g_counts[e];
    int row0 = rt * TM;
    if (row0 >= n_e) return;
    int n0 = blockIdx.y * TN;
    int tid = threadIdx.x;
    uint32_t sb = smem_u32(sh);

    // A staging: 2 threads per row; each stages 32B (16 halfs) of the 64B row
    const __half* aptr = nullptr;
    {
        int gs = row0 + (tid >> 1);
        if (gs < n_e) {
            if (MODE == 0) aptr = A + (size_t)g_tok[e * NT + gs] * HD;
            else           aptr = A + (size_t)(g_offsets[e] + gs) * ID;
        }
    }
    int ahalf = tid & 1;
    uint32_t a_dst = sb + (tid >> 1) * 80 + ahalf * 32;
    uint32_t avalid = aptr ? 16u : 0u;
    const __half* adummy = W;

    // B staging: 8 threads per row (32 rows); each stages 32B of the 256B row
    int brow = tid >> 3, bseg = tid & 7;
    const __half* wbase = W + (size_t)e * HD * ID
                            + (size_t)brow * NSW + n0 + bseg * 16;
    uint32_t b_dst = sb + ASZB + brow * 272 + bseg * 32;

    auto issue = [&](int kt) {
        uint32_t so = (uint32_t)((kt & (NSTAGE - 1)) * STAGE_B);
        int k0 = kt * BK;
        const __half* as = aptr ? (aptr + k0 + ahalf * 16) : adummy;
        cp16(a_dst + so,      as,     avalid);
        cp16(a_dst + so + 16, as + 8, avalid);
        const __half* bs = wbase + (size_t)k0 * NSW;
        cp16(b_dst + so,      bs,     16u);
        cp16(b_dst + so + 16, bs + 8, 16u);
        CP_COMMIT();
    };

    int wrp = tid >> 5, wm = wrp >> 1, wn = wrp & 1, lane = tid & 31;

    wmma::fragment<wmma::accumulator, 16, 16, 16, float> c[2][4];
#pragma unroll
    for (int i = 0; i < 2; i++)
#pragma unroll
        for (int j = 0; j < 4; j++) wmma::fill_fragment(c[i][j], 0.f);

    issue(0);
    if (KT > 1) issue(1);
    if (KT > 2) issue(2);

    for (int kt = 0; kt < KT; ++kt) {
        if (kt + 2 < KT)      asm volatile("cp.async.wait_group 2;" ::: "memory");
        else if (kt + 1 < KT) asm volatile("cp.async.wait_group 1;" ::: "memory");
        else                  asm volatile("cp.async.wait_group 0;" ::: "memory");
        __syncthreads();                 // stage kt visible; stage (kt+3)%4 readers retired
        if (kt + 3 < KT) issue(kt + 3);

        const __half* As = sh + (size_t)(kt & (NSTAGE - 1)) * STAGE_H;
        const __half* Bs = As + ASZ;
#pragma unroll
        for (int kk = 0; kk < 2; ++kk) {    // two k16 steps per BK=32 slice
            wmma::fragment<wmma::matrix_a, 16, 16, 16, half, wmma::row_major> af[2];
            wmma::fragment<wmma::matrix_b, 16, 16, 16, half, wmma::row_major> bf[4];
#pragma unroll
            for (int i = 0; i < 2; i++)
                wmma::load_matrix_sync(af[i], &As[(wm * 32 + i * 16) * LDA + kk * 16], LDA);
#pragma unroll
            for (int j = 0; j < 4; j++)
                wmma::load_matrix_sync(bf[j], &Bs[(kk * 16) * LDB + wn * 64 + j * 16], LDB);
#pragma unroll
            for (int i = 0; i < 2; i++)
#pragma unroll
                for (int j = 0; j < 4; j++)
                    wmma::mma_sync(c[i][j], af[i], bf[j], c[i][j]);
        }
    }
    __syncthreads();   // all MMAs done; stage smem reusable as epilogue patch

    int base_row = g_offsets[e] + row0;
    float* patch = reinterpret_cast<float*>(smem) + wrp * 320;   // 16x20 floats per warp
#pragma unroll
    for (int i = 0; i < 2; i++) {
#pragma unroll
        for (int j = 0; j < 4; j++) {
            wmma::store_matrix_sync(patch, c[i][j], 20, wmma::mem_row_major);
            __syncwarp();
            int lrb = wm * 32 + i * 16;
            int lcb = wn * 64 + j * 16;
#pragma unroll
            for (int q = 0; q < 8; q++) {
                int el = lane + q * 32;
                int r = el >> 4, cc = el & 15;
                int lr = lrb + r;
                if (row0 + lr < n_e) {
                    int gc = n0 + lcb + cc;
                    if (MODE == 0) {
                        float v = patch[r * 20 + cc] + bias[(size_t)e * ID + gc];
                        float sv = v / (1.f + expf(-v));
                        g_hdn[(size_t)(base_row + lr) * ID + gc] = __float2half_rn(sv);
                    } else {
                        g_y[(size_t)(base_row + lr) * HD + gc] = patch[r * 20 + cc];
                    }
                }
            }
            __syncwarp();
        }
    }
}

// ---------------- deterministic per-token combine ----------------
__global__ void combine_kernel(const float* __restrict__ b2, float* __restrict__ out) {
    int t = blockIdx.x;
    int e0 = g_meta_i[t * 4 + 0], s0 = g_meta_i[t * 4 + 1];
    int e1 = g_meta_i[t * 4 + 2], s1 = g_meta_i[t * 4 + 3];
    float w0 = g_meta_w[t * 2 + 0];
    float w1 = g_meta_w[t * 2 + 1];
    int r0 = g_offsets[e0] + s0;
    int r1 = g_offsets[e1] + s1;

    const float4* y0 = reinterpret_cast<const float4*>(g_y + (size_t)r0 * HD);
    const float4* y1 = reinterpret_cast<const float4*>(g_y + (size_t)r1 * HD);
    const float4* c0 = reinterpret_cast<const float4*>(b2 + (size_t)e0 * HD);
    const float4* c1 = reinterpret_cast<const float4*>(b2 + (size_t)e1 * HD);
    float4* o = reinterpret_cast<float4*>(out + (size_t)t * HD);

    int h = threadIdx.x;  // blockDim = 256 == HD/4
    float4 a = y0[h], b = y1[h], p = c0[h], q = c1[h];
    float4 rr;
    rr.x = w0 * (a.x + p.x) + w1 * (b.x + q.x);
    rr.y = w0 * (a.y + p.y) + w1 * (b.y + q.y);
    rr.z = w0 * (a.z + p.z) + w1 * (b.z + q.z);
    rr.w = w0 * (a.w + p.w) + w1 * (b.w + q.w);
    o[h] = rr;
}

// ---------------- launch ----------------
extern "C" void kernel_launch(void* const* d_in, const int* in_sizes, int n_in,
                              void* d_out, int out_size) {
    const float* x  = (const float*)d_in[0];
    const float* Wg = (const float*)d_in[1];
    const float* W1 = (const float*)d_in[2];
    const float* b1 = (const float*)d_in[3];
    const float* W2 = (const float*)d_in[4];
    const float* b2 = (const float*)d_in[5];
    float* out = (float*)d_out;

    cudaFuncSetAttribute(gemm_tc<0>, cudaFuncAttributeMaxDynamicSharedMemorySize, SMEM_BYTES);
    cudaFuncSetAttribute(gemm_tc<1>, cudaFuncAttributeMaxDynamicSharedMemorySize, SMEM_BYTES);

    // Device addresses of __device__ symbols (host symbol names are not device ptrs)
    __half* xh  = nullptr; cudaGetSymbolAddress((void**)&xh,  g_xh);
    __half* w1h = nullptr; cudaGetSymbolAddress((void**)&w1h, g_w1h);
    __half* w2h = nullptr; cudaGetSymbolAddress((void**)&w2h, g_w2h);
    __half* hdn = nullptr; cudaGetSymbolAddress((void**)&hdn, g_hdn);

    reset_kernel<<<1, 32>>>();
    gate_kernel<<<NT / 8, 256>>>(x, Wg);
    prefix_kernel<<<1, 32>>>();
    conv3_kernel<<<8192, 256>>>(
        (const float4*)x,  (h4*)xh,  NT * HD / 4,
        (const float4*)W1, (h4*)w1h, NE * HD * ID / 4,
        (const float4*)W2, (h4*)w2h, NE * ID * HD / 4);
    gemm_tc<0><<<dim3(NE * RTILES, ID / TN), 256, SMEM_BYTES>>>(xh,  w1h, b1);
    gemm_tc<1><<<dim3(NE * RTILES, HD / TN), 256, SMEM_BYTES>>>(hdn, w2h, b1);
    combine_kernel<<<NT, 256>>>(b2, out);
}